// round 16
// baseline (speedup 1.0000x reference)
#include <cuda_runtime.h>
#include <cuda_bf16.h>
#include <cuda_fp16.h>
#include <math.h>
#include <stdint.h>

#define TT 64
#define BB 32
#define HH 512
#define VV 32000
#define SS 64
#define MROWS (TT*BB)      // 2048
#define G4H (4*HH)         // 2048
#define KTOT 1024

// ---- static scratch ----
__device__ float g_x   [MROWS*HH];
__device__ float g_xw  [MROWS*G4H];          // input proj, transposed [gate_row][m]
__device__ float g_ys0 [MROWS*HH];
__device__ float g_ys1 [MROWS*HH];
__device__ float g_h0  [2][HH*BB];
__device__ float g_h1  [2][HH*BB];
__device__ float g_c0  [HH*BB];
__device__ float g_c1  [HH*BB];
__device__ float g_ctx [BB*HH];
__device__ int   g_bar [2*TT];
__device__ __half g_Ah[MROWS*KTOT];          // [dec|ctx] fp16 (single plane)
__device__ __half g_Wh[(size_t)VV*KTOT];     // W2 fp16 (single plane)
__device__ __nv_bfloat16 g_xh[MROWS*HH];     // x / ys0 split hi (bf16, xw gemm)
__device__ __nv_bfloat16 g_xl[MROWS*HH];
__device__ __nv_bfloat16 g_wih_h[G4H*HH];
__device__ __nv_bfloat16 g_wih_l[G4H*HH];

extern __shared__ char dynsmem[];

#define SWZ(o) ((o) ^ (((o) >> 3) & 0x70))

__device__ __forceinline__ uint32_t s2u(const void* p) {
    uint32_t a;
    asm("{ .reg .u64 t; cvta.to.shared.u64 t, %1; cvt.u32.u64 %0, t; }" : "=r"(a) : "l"(p));
    return a;
}
__device__ __forceinline__ void cp16(uint32_t smem, const void* g) {
    asm volatile("cp.async.cg.shared.global [%0], [%1], 16;" :: "r"(smem), "l"(g));
}
#define CP_COMMIT() asm volatile("cp.async.commit_group;" ::: "memory")
#define CP_WAIT1()  asm volatile("cp.async.wait_group 1;" ::: "memory")
#define CP_WAIT0()  asm volatile("cp.async.wait_group 0;" ::: "memory")

__device__ __forceinline__ void ldsm4(uint32_t* r, uint32_t addr) {
    asm volatile("ldmatrix.sync.aligned.m8n8.x4.shared.b16 {%0,%1,%2,%3}, [%4];"
        : "=r"(r[0]), "=r"(r[1]), "=r"(r[2]), "=r"(r[3]) : "r"(addr));
}
__device__ __forceinline__ void mma16816_bf(float* d, const uint32_t* a, const uint32_t* b) {
    asm volatile(
        "mma.sync.aligned.m16n8k16.row.col.f32.bf16.bf16.f32 "
        "{%0,%1,%2,%3}, {%4,%5,%6,%7}, {%8,%9}, {%0,%1,%2,%3};"
        : "+f"(d[0]), "+f"(d[1]), "+f"(d[2]), "+f"(d[3])
        : "r"(a[0]), "r"(a[1]), "r"(a[2]), "r"(a[3]), "r"(b[0]), "r"(b[1]));
}
__device__ __forceinline__ void mma16816_fp(float* d, const uint32_t* a, const uint32_t* b) {
    asm volatile(
        "mma.sync.aligned.m16n8k16.row.col.f32.f16.f16.f32 "
        "{%0,%1,%2,%3}, {%4,%5,%6,%7}, {%8,%9}, {%0,%1,%2,%3};"
        : "+f"(d[0]), "+f"(d[1]), "+f"(d[2]), "+f"(d[3])
        : "r"(a[0]), "r"(a[1]), "r"(a[2]), "r"(a[3]), "r"(b[0]), "r"(b[1]));
}

// ---- init / gather ----
__global__ void init_state(const float* __restrict__ hidden, const float* __restrict__ cell,
                           float* h0, float* h1, float* c0, float* c1, int* bar) {
    int idx = blockIdx.x * blockDim.x + threadIdx.x;
    if (idx < 2*TT) bar[idx] = 0;
    if (idx >= HH*BB) return;
    int j = idx >> 5, b = idx & 31;
    int src = b * HH + j;
    h0[idx] = hidden[src];  h1[idx] = hidden[HH*BB + src];
    c0[idx] = cell[src];    c1[idx] = cell[HH*BB + src];
}
__global__ void gather_emb(const int* __restrict__ tgt, const float* __restrict__ emb,
                           float* __restrict__ x) {
    int m = blockIdx.x, r = tgt[m];
    reinterpret_cast<float4*>(x + (size_t)m * HH)[threadIdx.x] =
        reinterpret_cast<const float4*>(emb + (size_t)r * HH)[threadIdx.x];
}

// ---- fp32 -> bf16 hi/lo split (for xw GEMM) ----
__device__ __forceinline__ void split8(const float* src, __nv_bfloat16* hi, __nv_bfloat16* lo) {
    float4 f0 = *reinterpret_cast<const float4*>(src);
    float4 f1 = *reinterpret_cast<const float4*>(src + 4);
    float fv[8] = {f0.x,f0.y,f0.z,f0.w,f1.x,f1.y,f1.z,f1.w};
    __nv_bfloat16 h8[8], l8[8];
    #pragma unroll
    for (int q = 0; q < 8; q++) {
        h8[q] = __float2bfloat16_rn(fv[q]);
        l8[q] = __float2bfloat16_rn(fv[q] - __bfloat162float(h8[q]));
    }
    *reinterpret_cast<uint4*>(hi) = *reinterpret_cast<uint4*>(h8);
    *reinterpret_cast<uint4*>(lo) = *reinterpret_cast<uint4*>(l8);
}
__global__ void conv_flat(const float* __restrict__ src, __nv_bfloat16* hi, __nv_bfloat16* lo) {
    size_t i = ((size_t)blockIdx.x * blockDim.x + threadIdx.x) * 8;
    split8(src + i, hi + i, lo + i);
}

// ---- fp32 -> fp16 single-plane converters (for logits GEMM) ----
__device__ __forceinline__ void cvt8h(const float* src, __half* dst) {
    float4 f0 = *reinterpret_cast<const float4*>(src);
    float4 f1 = *reinterpret_cast<const float4*>(src + 4);
    float fv[8] = {f0.x,f0.y,f0.z,f0.w,f1.x,f1.y,f1.z,f1.w};
    __half h8[8];
    #pragma unroll
    for (int q = 0; q < 8; q++) h8[q] = __float2half_rn(fv[q]);
    *reinterpret_cast<uint4*>(dst) = *reinterpret_cast<uint4*>(h8);
}
__global__ void conv_w_h(const float* __restrict__ W2, __half* __restrict__ dst) {
    size_t i = ((size_t)blockIdx.x * blockDim.x + threadIdx.x) * 8;
    cvt8h(W2 + i, dst + i);
}
__global__ void conv_a_h(const float* __restrict__ dec, const float* __restrict__ ctx,
                         __half* __restrict__ dst) {
    int m = blockIdx.x, t8 = threadIdx.x * 8;
    const float* src = (t8 < HH) ? dec + (size_t)m*HH + t8
                                 : ctx + (size_t)(m & 31)*HH + (t8 - HH);
    cvt8h(src, dst + (size_t)m * KTOT + t8);
}

// ---- mma input-projection GEMM (bf16 3-pass, validated) --------------------
#define PLANE 16384
#define BUFSTR4 (4*PLANE)
#define GSMEM_XW (2*BUFSTR4)     // 128 KB

__global__ __launch_bounds__(256, 1)
void gemm_xw_mma(const __nv_bfloat16* __restrict__ Ah, const __nv_bfloat16* __restrict__ Al,
                 const __nv_bfloat16* __restrict__ Bh, const __nv_bfloat16* __restrict__ Bl,
                 float* __restrict__ C,
                 const float* __restrict__ bias0, const float* __restrict__ bias1) {
    uint32_t sb = s2u(dynsmem);
    int tid = threadIdx.x, wid = tid >> 5, lane = tid & 31;
    int bm = blockIdx.x * 128, bn = blockIdx.y * 128;
    int wm = (wid & 3) * 32, wn = (wid >> 2) * 64;

    float acc[2][8][4];
    #pragma unroll
    for (int mt = 0; mt < 2; mt++)
        #pragma unroll
        for (int nt = 0; nt < 8; nt++)
            #pragma unroll
            for (int q = 0; q < 4; q++) acc[mt][nt][q] = 0.f;

    const __nv_bfloat16* gsrc[4] = {Ah, Al, Bh, Bl};
    auto fill = [&](int c, int buf) {
        uint32_t base = sb + buf * BUFSTR4;
        #pragma unroll
        for (int it = 0; it < 16; it++) {
            int i = tid + it * 256;
            int p = i >> 10, j = i & 1023;
            int r = j >> 3, seg = j & 7;
            int grow = (p < 2) ? (bm + r) : (bn + r);
            const __nv_bfloat16* g = gsrc[p] + ((size_t)grow << 9) + (c << 6) + (seg << 3);
            cp16(base + p * PLANE + SWZ((uint32_t)(r * 128 + seg * 16)), g);
        }
        CP_COMMIT();
    };

    fill(0, 0);
    for (int c = 0; c < 8; c++) {
        int buf = c & 1;
        if (c + 1 < 8) { fill(c + 1, buf ^ 1); CP_WAIT1(); }
        else           { CP_WAIT0(); }
        __syncthreads();
        uint32_t base = sb + buf * BUFSTR4;
        #pragma unroll
        for (int kk = 0; kk < 4; kk++) {
            uint32_t afh[2][4], afl[2][4];
            #pragma unroll
            for (int mt = 0; mt < 2; mt++) {
                int r = wm + mt * 16 + (lane & 15);
                uint32_t off = SWZ((uint32_t)(r * 128 + kk * 32 + (lane >> 4) * 16));
                ldsm4(afh[mt], base + 0 * PLANE + off);
                ldsm4(afl[mt], base + 1 * PLANE + off);
            }
            uint32_t bfh[4][4], bfl[4][4];
            #pragma unroll
            for (int np = 0; np < 4; np++) {
                int nrow = wn + np * 16 + (lane & 7) + ((lane >> 4) << 3);
                uint32_t off = SWZ((uint32_t)(nrow * 128 + kk * 32 + ((lane >> 3) & 1) * 16));
                ldsm4(bfh[np], base + 2 * PLANE + off);
                ldsm4(bfl[np], base + 3 * PLANE + off);
            }
            #pragma unroll
            for (int mt = 0; mt < 2; mt++)
                #pragma unroll
                for (int nt = 0; nt < 8; nt++) {
                    const uint32_t* bh = &bfh[nt >> 1][(nt & 1) * 2];
                    const uint32_t* bl = &bfl[nt >> 1][(nt & 1) * 2];
                    mma16816_bf(acc[mt][nt], afh[mt], bh);
                    mma16816_bf(acc[mt][nt], afh[mt], bl);
                    mma16816_bf(acc[mt][nt], afl[mt], bh);
                }
        }
        __syncthreads();
    }
    #pragma unroll
    for (int mt = 0; mt < 2; mt++) {
        int r0 = bm + wm + mt * 16 + (lane >> 2);
        #pragma unroll
        for (int nt = 0; nt < 8; nt++) {
            int n0 = bn + wn + nt * 8 + (lane & 3) * 2;
            float b0 = bias0[n0] + bias1[n0];
            float b1 = bias0[n0+1] + bias1[n0+1];
            C[(size_t)n0     * MROWS + r0]     = acc[mt][nt][0] + b0;
            C[(size_t)(n0+1) * MROWS + r0]     = acc[mt][nt][1] + b1;
            C[(size_t)n0     * MROWS + r0 + 8] = acc[mt][nt][2] + b0;
            C[(size_t)(n0+1) * MROWS + r0 + 8] = acc[mt][nt][3] + b1;
        }
    }
}

// ---- persistent LSTM: split-K x4 (512 threads), tight-poll barrier ----------
__device__ __forceinline__ float sigmoidf_(float x) { return 1.f / (1.f + expf(-x)); }

__global__ __launch_bounds__(512)
void lstm_persist(const float* __restrict__ xwT, const float* __restrict__ W_hh,
                  float* __restrict__ hbuf, float* __restrict__ cbuf,
                  float* __restrict__ ys, int* __restrict__ bar) {
    float* smemf = reinterpret_cast<float*>(dynsmem);
    float* Ws = smemf;                 // 16 x 512
    float* Hs = smemf + 4*4*HH;        // 512 x 32
    float* Ps = Hs + HH*BB;            // partials [3][4][4][32]

    int tid = threadIdx.x, w = tid >> 5, b = tid & 31, cta = blockIdx.x;
    int q = w >> 2, jl = w & 3;
    int jg = cta * 4 + jl;

    #pragma unroll
    for (int it = 0; it < 4; it++) {
        int idx = tid + it * 512;
        int row = idx >> 7, col4 = idx & 127;
        int g = row >> 2, j2 = row & 3;
        reinterpret_cast<float4*>(Ws)[row * 128 + col4] =
            reinterpret_cast<const float4*>(W_hh + (size_t)(g*HH + cta*4 + j2) * HH)[col4];
    }
    float creg = (q == 0) ? cbuf[jg*32 + b] : 0.f;
    __syncthreads();

    const float4* wi = reinterpret_cast<const float4*>(&Ws[(0*4 + jl) * HH]) + q*32;
    const float4* wf = reinterpret_cast<const float4*>(&Ws[(1*4 + jl) * HH]) + q*32;
    const float4* wg = reinterpret_cast<const float4*>(&Ws[(2*4 + jl) * HH]) + q*32;
    const float4* wo = reinterpret_cast<const float4*>(&Ws[(3*4 + jl) * HH]) + q*32;
    const float* Hh = Hs + q * 128 * 32;

    volatile int* vbar = (volatile int*)bar;

    for (int t = 0; t < TT; t++) {
        int m = t*32 + b;
        // gate-bias loads first: independent of h -> overlap with staging
        float ai0 = 0.f, af0 = 0.f, ag0 = 0.f, ao0 = 0.f;
        float ai1 = 0.f, af1 = 0.f, ag1 = 0.f, ao1 = 0.f;
        if (q == 0) {
            ai0 = xwT[(size_t)(0*HH + jg) * MROWS + m];
            af0 = xwT[(size_t)(1*HH + jg) * MROWS + m];
            ag0 = xwT[(size_t)(2*HH + jg) * MROWS + m];
            ao0 = xwT[(size_t)(3*HH + jg) * MROWS + m];
        }
        {   // stage h(t): 4096 float4 over 512 threads
            const float4* hsrc = reinterpret_cast<const float4*>(hbuf + (t & 1) * HH*BB);
            float4* hdst = reinterpret_cast<float4*>(Hs);
            #pragma unroll
            for (int i = 0; i < 8; i++)
                hdst[tid + (i << 9)] = __ldcg(hsrc + tid + (i << 9));
        }
        __syncthreads();

        #pragma unroll 8
        for (int k4 = 0; k4 < 32; k4 += 2) {
            {
                float4 vi = wi[k4], vf = wf[k4], vg = wg[k4], vo = wo[k4];
                int k = k4 << 2;
                float h0 = Hh[(k+0)*32 + b], h1 = Hh[(k+1)*32 + b];
                float h2 = Hh[(k+2)*32 + b], h3 = Hh[(k+3)*32 + b];
                ai0 = fmaf(vi.x,h0,ai0); af0 = fmaf(vf.x,h0,af0); ag0 = fmaf(vg.x,h0,ag0); ao0 = fmaf(vo.x,h0,ao0);
                ai0 = fmaf(vi.y,h1,ai0); af0 = fmaf(vf.y,h1,af0); ag0 = fmaf(vg.y,h1,ag0); ao0 = fmaf(vo.y,h1,ao0);
                ai0 = fmaf(vi.z,h2,ai0); af0 = fmaf(vf.z,h2,af0); ag0 = fmaf(vg.z,h2,ag0); ao0 = fmaf(vo.z,h2,ao0);
                ai0 = fmaf(vi.w,h3,ai0); af0 = fmaf(vf.w,h3,af0); ag0 = fmaf(vg.w,h3,ag0); ao0 = fmaf(vo.w,h3,ao0);
            }
            {
                float4 vi = wi[k4+1], vf = wf[k4+1], vg = wg[k4+1], vo = wo[k4+1];
                int k = (k4+1) << 2;
                float h0 = Hh[(k+0)*32 + b], h1 = Hh[(k+1)*32 + b];
                float h2 = Hh[(k+2)*32 + b], h3 = Hh[(k+3)*32 + b];
                ai1 = fmaf(vi.x,h0,ai1); af1 = fmaf(vf.x,h0,af1); ag1 = fmaf(vg.x,h0,ag1); ao1 = fmaf(vo.x,h0,ao1);
                ai1 = fmaf(vi.y,h1,ai1); af1 = fmaf(vf.y,h1,af1); ag1 = fmaf(vg.y,h1,ag1); ao1 = fmaf(vo.y,h1,ao1);
                ai1 = fmaf(vi.z,h2,ai1); af1 = fmaf(vf.z,h2,af1); ag1 = fmaf(vg.z,h2,ag1); ao1 = fmaf(vo.z,h2,ao1);
                ai1 = fmaf(vi.w,h3,ai1); af1 = fmaf(vf.w,h3,af1); ag1 = fmaf(vg.w,h3,ag1); ao1 = fmaf(vo.w,h3,ao1);
            }
        }
        float ai = ai0 + ai1, af = af0 + af1, ag = ag0 + ag1, ao = ao0 + ao1;

        if (q != 0) {
            int o = jl*32 + b;
            Ps[(q-1)*512 + 0*128 + o] = ai;
            Ps[(q-1)*512 + 1*128 + o] = af;
            Ps[(q-1)*512 + 2*128 + o] = ag;
            Ps[(q-1)*512 + 3*128 + o] = ao;
        }
        __syncthreads();
        if (q == 0) {
            int o = jl*32 + b;
            ai += Ps[0*512 + 0*128 + o] + Ps[1*512 + 0*128 + o] + Ps[2*512 + 0*128 + o];
            af += Ps[0*512 + 1*128 + o] + Ps[1*512 + 1*128 + o] + Ps[2*512 + 1*128 + o];
            ag += Ps[0*512 + 2*128 + o] + Ps[1*512 + 2*128 + o] + Ps[2*512 + 2*128 + o];
            ao += Ps[0*512 + 3*128 + o] + Ps[1*512 + 3*128 + o] + Ps[2*512 + 3*128 + o];
            float ig = sigmoidf_(ai), fg = sigmoidf_(af);
            float gg = tanhf(ag),    og = sigmoidf_(ao);
            float c_new = fmaf(fg, creg, ig * gg);
            float h_new = og * tanhf(c_new);
            creg = c_new;
            hbuf[((t+1)&1) * HH*BB + jg*32 + b] = h_new;
            ys[(size_t)m * HH + jg] = h_new;
            if (t == TT-1) cbuf[jg*32 + b] = creg;
            __threadfence();
        }
        __syncthreads();
        if (tid == 0) {
            atomicAdd(&bar[t], 1);
            while (vbar[t] < (int)gridDim.x) { }
            __threadfence();
        }
        __syncthreads();
    }
}

// ---- ctx: exact softmax shortcut = masked mean over S ----
__global__ void ctx_kernel(const float* __restrict__ enc, const int* __restrict__ src_mask,
                           float* __restrict__ ctx) {
    int b = blockIdx.x, h = threadIdx.x;
    float s_un = 0.f, s_all = 0.f; int cnt = 0;
    #pragma unroll 4
    for (int s = 0; s < SS; s++) {
        float v = enc[((size_t)s * BB + b) * HH + h];
        s_all += v;
        if (src_mask[s * BB + b] == 0) { s_un += v; cnt++; }
    }
    ctx[b * HH + h] = (cnt > 0) ? (s_un / (float)cnt) : (s_all / (float)SS);
}

// ---- fp16 single-pass logits GEMM: out[2048,32000] = Acat @ W2cat^T --------
// err ~2e-4 (norm): per-side fp16 rounding 2^-12 rms. 2 planes, double buffer.
#define CHUNKS 16
#define BUFSTR2 (2*PLANE)
#define GSMEM_LG (2*BUFSTR2)     // 64 KB

__global__ __launch_bounds__(256, 1)
void gemm_logits_mma(const __half* __restrict__ Ah, const __half* __restrict__ Bh,
                     float* __restrict__ out) {
    uint32_t sb = s2u(dynsmem);
    int tid = threadIdx.x, wid = tid >> 5, lane = tid & 31;
    int bm = blockIdx.x * 128, bn = blockIdx.y * 128;
    int wm = (wid & 3) * 32, wn = (wid >> 2) * 64;

    float acc[2][8][4];
    #pragma unroll
    for (int mt = 0; mt < 2; mt++)
        #pragma unroll
        for (int nt = 0; nt < 8; nt++)
            #pragma unroll
            for (int q = 0; q < 4; q++) acc[mt][nt][q] = 0.f;

    const __half* gsrc[2] = {Ah, Bh};
    auto fill = [&](int c, int buf) {
        uint32_t base = sb + buf * BUFSTR2;
        #pragma unroll
        for (int it = 0; it < 8; it++) {
            int i = tid + it * 256;
            int p = i >> 10, j = i & 1023;
            int r = j >> 3, seg = j & 7;
            int grow = (p == 0) ? (bm + r) : (bn + r);
            const __half* g = gsrc[p] + ((size_t)grow << 10) + (c << 6) + (seg << 3);
            cp16(base + p * PLANE + SWZ((uint32_t)(r * 128 + seg * 16)), g);
        }
        CP_COMMIT();
    };

    fill(0, 0);
    for (int c = 0; c < CHUNKS; c++) {
        int buf = c & 1;
        if (c + 1 < CHUNKS) { fill(c + 1, buf ^ 1); CP_WAIT1(); }
        else                { CP_WAIT0(); }
        __syncthreads();
        uint32_t base = sb + buf * BUFSTR2;
        #pragma unroll
        for (int kk = 0; kk < 4; kk++) {
            uint32_t af[2][4];
            #pragma unroll
            for (int mt = 0; mt < 2; mt++) {
                int r = wm + mt * 16 + (lane & 15);
                uint32_t off = SWZ((uint32_t)(r * 128 + kk * 32 + (lane >> 4) * 16));
                ldsm4(af[mt], base + 0 * PLANE + off);
            }
            uint32_t bf[4][4];
            #pragma unroll
            for (int np = 0; np < 4; np++) {
                int nrow = wn + np * 16 + (lane & 7) + ((lane >> 4) << 3);
                uint32_t off = SWZ((uint32_t)(nrow * 128 + kk * 32 + ((lane >> 3) & 1) * 16));
                ldsm4(bf[np], base + 1 * PLANE + off);
            }
            #pragma unroll
            for (int mt = 0; mt < 2; mt++)
                #pragma unroll
                for (int nt = 0; nt < 8; nt++)
                    mma16816_fp(acc[mt][nt], af[mt], &bf[nt >> 1][(nt & 1) * 2]);
        }
        __syncthreads();
    }
    #pragma unroll
    for (int mt = 0; mt < 2; mt++) {
        int r0 = bm + wm + mt * 16 + (lane >> 2);
        #pragma unroll
        for (int nt = 0; nt < 8; nt++) {
            int cidx = bn + wn + nt * 8 + (lane & 3) * 2;
            *reinterpret_cast<float2*>(out + (size_t)r0 * VV + cidx) =
                make_float2(acc[mt][nt][0], acc[mt][nt][1]);
            *reinterpret_cast<float2*>(out + (size_t)(r0 + 8) * VV + cidx) =
                make_float2(acc[mt][nt][2], acc[mt][nt][3]);
        }
    }
}

// ---- tail: hs / cs ----
__global__ void tail_kernel(const float* __restrict__ ys0, const float* __restrict__ ys1,
                            const float* __restrict__ c0, const float* __restrict__ c1,
                            float* __restrict__ out) {
    int idx = blockIdx.x * blockDim.x + threadIdx.x;
    if (idx >= 4*HH*BB) return;
    int seg = idx >> 14, i = idx & 16383;
    int b = i >> 9, j = i & 511;
    float v;
    if      (seg == 0) v = ys0[((size_t)(TT-1)*BB + b) * HH + j];
    else if (seg == 1) v = ys1[((size_t)(TT-1)*BB + b) * HH + j];
    else if (seg == 2) v = c0[j*32 + b];
    else               v = c1[j*32 + b];
    out[(size_t)MROWS * VV + idx] = v;
}

// ---- launch ----
extern "C" void kernel_launch(void* const* d_in, const int* in_sizes, int n_in,
                              void* d_out, int out_size) {
    (void)in_sizes; (void)n_in; (void)out_size;
    const int*   tgt     = (const int*)  d_in[0];
    const float* hidden  = (const float*)d_in[1];
    const float* cell    = (const float*)d_in[2];
    const float* enc     = (const float*)d_in[3];
    const int*   srcmask = (const int*)  d_in[4];
    const float* emb     = (const float*)d_in[5];
    const float* Wih0    = (const float*)d_in[6];
    const float* Whh0    = (const float*)d_in[7];
    const float* bih0    = (const float*)d_in[8];
    const float* bhh0    = (const float*)d_in[9];
    const float* Wih1    = (const float*)d_in[10];
    const float* Whh1    = (const float*)d_in[11];
    const float* bih1    = (const float*)d_in[12];
    const float* bhh1    = (const float*)d_in[13];
    // d_in[14] = W1: provably irrelevant (softmax shortcut)
    const float* W2      = (const float*)d_in[15];
    float* out = (float*)d_out;

    float *p_x, *p_xw, *p_ys0, *p_ys1, *p_h0, *p_h1, *p_c0, *p_c1, *p_ctx;
    __half *p_Ah, *p_Wh;
    __nv_bfloat16 *p_xh, *p_xl, *p_wih_h, *p_wih_l;
    int *p_bar;
    cudaGetSymbolAddress((void**)&p_x,     g_x);
    cudaGetSymbolAddress((void**)&p_xw,    g_xw);
    cudaGetSymbolAddress((void**)&p_ys0,   g_ys0);
    cudaGetSymbolAddress((void**)&p_ys1,   g_ys1);
    cudaGetSymbolAddress((void**)&p_h0,    g_h0);
    cudaGetSymbolAddress((void**)&p_h1,    g_h1);
    cudaGetSymbolAddress((void**)&p_c0,    g_c0);
    cudaGetSymbolAddress((void**)&p_c1,    g_c1);
    cudaGetSymbolAddress((void**)&p_ctx,   g_ctx);
    cudaGetSymbolAddress((void**)&p_Ah,    g_Ah);
    cudaGetSymbolAddress((void**)&p_Wh,    g_Wh);
    cudaGetSymbolAddress((void**)&p_xh,    g_xh);
    cudaGetSymbolAddress((void**)&p_xl,    g_xl);
    cudaGetSymbolAddress((void**)&p_wih_h, g_wih_h);
    cudaGetSymbolAddress((void**)&p_wih_l, g_wih_l);
    cudaGetSymbolAddress((void**)&p_bar,   g_bar);

    const int PERSIST_SMEM = (4*4*HH + HH*BB + 1536) * sizeof(float);  // ~104 KB
    cudaFuncSetAttribute(lstm_persist, cudaFuncAttributeMaxDynamicSharedMemorySize, PERSIST_SMEM);
    cudaFuncSetAttribute(gemm_logits_mma, cudaFuncAttributeMaxDynamicSharedMemorySize, GSMEM_LG);
    cudaFuncSetAttribute(gemm_xw_mma, cudaFuncAttributeMaxDynamicSharedMemorySize, GSMEM_XW);

    init_state<<<64, 256>>>(hidden, cell, p_h0, p_h1, p_c0, p_c1, p_bar);
    gather_emb<<<MROWS, 128>>>(tgt, emb, p_x);
    conv_w_h<<<(int)(((size_t)VV*KTOT)/8/256), 256>>>(W2, p_Wh);

    // layer 0
    conv_flat<<<512, 256>>>(p_x, p_xh, p_xl);
    conv_flat<<<512, 256>>>(Wih0, p_wih_h, p_wih_l);
    gemm_xw_mma<<<dim3(16, 16), 256, GSMEM_XW>>>(p_xh, p_xl, p_wih_h, p_wih_l, p_xw, bih0, bhh0);
    lstm_persist<<<128, 512, PERSIST_SMEM>>>(p_xw, Whh0, p_h0, p_c0, p_ys0, p_bar);

    // layer 1
    conv_flat<<<512, 256>>>(p_ys0, p_xh, p_xl);
    conv_flat<<<512, 256>>>(Wih1, p_wih_h, p_wih_l);
    gemm_xw_mma<<<dim3(16, 16), 256, GSMEM_XW>>>(p_xh, p_xl, p_wih_h, p_wih_l, p_xw, bih1, bhh1);
    lstm_persist<<<128, 512, PERSIST_SMEM>>>(p_xw, Whh1, p_h1, p_c1, p_ys1, p_bar + TT);

    ctx_kernel<<<BB, HH>>>(enc, srcmask, p_ctx);
    conv_a_h<<<MROWS, 128>>>(p_ys1, p_ctx, p_Ah);
    gemm_logits_mma<<<dim3(MROWS/128, VV/128), 256, GSMEM_LG>>>(p_Ah, p_Wh, out);

    tail_kernel<<<64, 1024>>>(p_ys0, p_ys1, p_c0, p_c1, out);
}

// round 17
// speedup vs baseline: 1.0992x; 1.0992x over previous
#include <cuda_runtime.h>
#include <cuda_bf16.h>
#include <cuda_fp16.h>
#include <math.h>
#include <stdint.h>

#define TT 64
#define BB 32
#define HH 512
#define VV 32000
#define SS 64
#define MROWS (TT*BB)      // 2048
#define G4H (4*HH)         // 2048
#define KTOT 1024

// ---- static scratch ----
__device__ float g_x   [MROWS*HH];
__device__ float g_xw  [MROWS*G4H];          // input proj, transposed [gate_row][m]
__device__ float g_ys0 [MROWS*HH];
__device__ float g_ys1 [MROWS*HH];
__device__ __half g_h0h[2][HH*BB];           // layer0 h ping-pong, [b][k], fp16 hi
__device__ __half g_h0l[2][HH*BB];           // fp16 lo
__device__ __half g_h1h[2][HH*BB];
__device__ __half g_h1l[2][HH*BB];
__device__ float g_c0  [HH*BB];              // c transposed [j*32+b]
__device__ float g_c1  [HH*BB];
__device__ float g_ctx [BB*HH];
__device__ int   g_bar [2*TT];
__device__ __half g_Ah[MROWS*KTOT];          // [dec|ctx] fp16 (logits A)
__device__ __half g_Wh[(size_t)VV*KTOT];     // W2 fp16
__device__ __nv_bfloat16 g_xh[MROWS*HH];     // bf16 hi/lo for xw GEMM
__device__ __nv_bfloat16 g_xl[MROWS*HH];
__device__ __nv_bfloat16 g_wih_h[G4H*HH];
__device__ __nv_bfloat16 g_wih_l[G4H*HH];

extern __shared__ char dynsmem[];

#define SWZ(o) ((o) ^ (((o) >> 3) & 0x70))

__device__ __forceinline__ uint32_t s2u(const void* p) {
    uint32_t a;
    asm("{ .reg .u64 t; cvta.to.shared.u64 t, %1; cvt.u32.u64 %0, t; }" : "=r"(a) : "l"(p));
    return a;
}
__device__ __forceinline__ void cp16(uint32_t smem, const void* g) {
    asm volatile("cp.async.cg.shared.global [%0], [%1], 16;" :: "r"(smem), "l"(g));
}
#define CP_COMMIT() asm volatile("cp.async.commit_group;" ::: "memory")
#define CP_WAIT1()  asm volatile("cp.async.wait_group 1;" ::: "memory")
#define CP_WAIT0()  asm volatile("cp.async.wait_group 0;" ::: "memory")

__device__ __forceinline__ void ldsm4(uint32_t* r, uint32_t addr) {
    asm volatile("ldmatrix.sync.aligned.m8n8.x4.shared.b16 {%0,%1,%2,%3}, [%4];"
        : "=r"(r[0]), "=r"(r[1]), "=r"(r[2]), "=r"(r[3]) : "r"(addr));
}
__device__ __forceinline__ void mma16816_bf(float* d, const uint32_t* a, const uint32_t* b) {
    asm volatile(
        "mma.sync.aligned.m16n8k16.row.col.f32.bf16.bf16.f32 "
        "{%0,%1,%2,%3}, {%4,%5,%6,%7}, {%8,%9}, {%0,%1,%2,%3};"
        : "+f"(d[0]), "+f"(d[1]), "+f"(d[2]), "+f"(d[3])
        : "r"(a[0]), "r"(a[1]), "r"(a[2]), "r"(a[3]), "r"(b[0]), "r"(b[1]));
}
__device__ __forceinline__ void mma16816_fp(float* d, const uint32_t* a, const uint32_t* b) {
    asm volatile(
        "mma.sync.aligned.m16n8k16.row.col.f32.f16.f16.f32 "
        "{%0,%1,%2,%3}, {%4,%5,%6,%7}, {%8,%9}, {%0,%1,%2,%3};"
        : "+f"(d[0]), "+f"(d[1]), "+f"(d[2]), "+f"(d[3])
        : "r"(a[0]), "r"(a[1]), "r"(a[2]), "r"(a[3]), "r"(b[0]), "r"(b[1]));
}

// ---- init: h planes (fp16 hi/lo, [b][k] = same linear layout as input) -----
__global__ void init_state(const float* __restrict__ hidden, const float* __restrict__ cell,
                           __half* h0h, __half* h0l, __half* h1h, __half* h1l,
                           float* c0, float* c1, int* bar) {
    int idx = blockIdx.x * blockDim.x + threadIdx.x;   // 0..16383
    if (idx < 2*TT) bar[idx] = 0;
    if (idx >= HH*BB) return;
    float v0 = hidden[idx];
    float v1 = hidden[HH*BB + idx];
    __half a = __float2half_rn(v0);
    h0h[idx] = a; h0l[idx] = __float2half_rn(v0 - __half2float(a));
    __half bq = __float2half_rn(v1);
    h1h[idx] = bq; h1l[idx] = __float2half_rn(v1 - __half2float(bq));
    // c transposed [j*32+b] from [b][j]
    int b = idx >> 9, j = idx & 511;
    c0[j*32 + b] = cell[idx];
    c1[j*32 + b] = cell[HH*BB + idx];
}
__global__ void gather_emb(const int* __restrict__ tgt, const float* __restrict__ emb,
                           float* __restrict__ x) {
    int m = blockIdx.x, r = tgt[m];
    reinterpret_cast<float4*>(x + (size_t)m * HH)[threadIdx.x] =
        reinterpret_cast<const float4*>(emb + (size_t)r * HH)[threadIdx.x];
}

// ---- fp32 -> bf16 hi/lo (xw GEMM inputs) ----
__device__ __forceinline__ void split8(const float* src, __nv_bfloat16* hi, __nv_bfloat16* lo) {
    float4 f0 = *reinterpret_cast<const float4*>(src);
    float4 f1 = *reinterpret_cast<const float4*>(src + 4);
    float fv[8] = {f0.x,f0.y,f0.z,f0.w,f1.x,f1.y,f1.z,f1.w};
    __nv_bfloat16 h8[8], l8[8];
    #pragma unroll
    for (int q = 0; q < 8; q++) {
        h8[q] = __float2bfloat16_rn(fv[q]);
        l8[q] = __float2bfloat16_rn(fv[q] - __bfloat162float(h8[q]));
    }
    *reinterpret_cast<uint4*>(hi) = *reinterpret_cast<uint4*>(h8);
    *reinterpret_cast<uint4*>(lo) = *reinterpret_cast<uint4*>(l8);
}
__global__ void conv_flat(const float* __restrict__ src, __nv_bfloat16* hi, __nv_bfloat16* lo) {
    size_t i = ((size_t)blockIdx.x * blockDim.x + threadIdx.x) * 8;
    split8(src + i, hi + i, lo + i);
}

// ---- fp32 -> fp16 (logits GEMM inputs) ----
__device__ __forceinline__ void cvt8h(const float* src, __half* dst) {
    float4 f0 = *reinterpret_cast<const float4*>(src);
    float4 f1 = *reinterpret_cast<const float4*>(src + 4);
    float fv[8] = {f0.x,f0.y,f0.z,f0.w,f1.x,f1.y,f1.z,f1.w};
    __half h8[8];
    #pragma unroll
    for (int q = 0; q < 8; q++) h8[q] = __float2half_rn(fv[q]);
    *reinterpret_cast<uint4*>(dst) = *reinterpret_cast<uint4*>(h8);
}
__global__ void conv_w_h(const float* __restrict__ W2, __half* __restrict__ dst) {
    size_t i = ((size_t)blockIdx.x * blockDim.x + threadIdx.x) * 8;
    cvt8h(W2 + i, dst + i);
}
__global__ void conv_a_h(const float* __restrict__ dec, const float* __restrict__ ctx,
                         __half* __restrict__ dst) {
    int m = blockIdx.x, t8 = threadIdx.x * 8;
    const float* src = (t8 < HH) ? dec + (size_t)m*HH + t8
                                 : ctx + (size_t)(m & 31)*HH + (t8 - HH);
    cvt8h(src, dst + (size_t)m * KTOT + t8);
}

// ---- mma input-projection GEMM (bf16 3-pass, validated) --------------------
#define PLANE 16384
#define BUFSTR4 (4*PLANE)
#define GSMEM_XW (2*BUFSTR4)     // 128 KB

__global__ __launch_bounds__(256, 1)
void gemm_xw_mma(const __nv_bfloat16* __restrict__ Ah, const __nv_bfloat16* __restrict__ Al,
                 const __nv_bfloat16* __restrict__ Bh, const __nv_bfloat16* __restrict__ Bl,
                 float* __restrict__ C,
                 const float* __restrict__ bias0, const float* __restrict__ bias1) {
    uint32_t sb = s2u(dynsmem);
    int tid = threadIdx.x, wid = tid >> 5, lane = tid & 31;
    int bm = blockIdx.x * 128, bn = blockIdx.y * 128;
    int wm = (wid & 3) * 32, wn = (wid >> 2) * 64;

    float acc[2][8][4];
    #pragma unroll
    for (int mt = 0; mt < 2; mt++)
        #pragma unroll
        for (int nt = 0; nt < 8; nt++)
            #pragma unroll
            for (int q = 0; q < 4; q++) acc[mt][nt][q] = 0.f;

    const __nv_bfloat16* gsrc[4] = {Ah, Al, Bh, Bl};
    auto fill = [&](int c, int buf) {
        uint32_t base = sb + buf * BUFSTR4;
        #pragma unroll
        for (int it = 0; it < 16; it++) {
            int i = tid + it * 256;
            int p = i >> 10, j = i & 1023;
            int r = j >> 3, seg = j & 7;
            int grow = (p < 2) ? (bm + r) : (bn + r);
            const __nv_bfloat16* g = gsrc[p] + ((size_t)grow << 9) + (c << 6) + (seg << 3);
            cp16(base + p * PLANE + SWZ((uint32_t)(r * 128 + seg * 16)), g);
        }
        CP_COMMIT();
    };

    fill(0, 0);
    for (int c = 0; c < 8; c++) {
        int buf = c & 1;
        if (c + 1 < 8) { fill(c + 1, buf ^ 1); CP_WAIT1(); }
        else           { CP_WAIT0(); }
        __syncthreads();
        uint32_t base = sb + buf * BUFSTR4;
        #pragma unroll
        for (int kk = 0; kk < 4; kk++) {
            uint32_t afh[2][4], afl[2][4];
            #pragma unroll
            for (int mt = 0; mt < 2; mt++) {
                int r = wm + mt * 16 + (lane & 15);
                uint32_t off = SWZ((uint32_t)(r * 128 + kk * 32 + (lane >> 4) * 16));
                ldsm4(afh[mt], base + 0 * PLANE + off);
                ldsm4(afl[mt], base + 1 * PLANE + off);
            }
            uint32_t bfh[4][4], bfl[4][4];
            #pragma unroll
            for (int np = 0; np < 4; np++) {
                int nrow = wn + np * 16 + (lane & 7) + ((lane >> 4) << 3);
                uint32_t off = SWZ((uint32_t)(nrow * 128 + kk * 32 + ((lane >> 3) & 1) * 16));
                ldsm4(bfh[np], base + 2 * PLANE + off);
                ldsm4(bfl[np], base + 3 * PLANE + off);
            }
            #pragma unroll
            for (int mt = 0; mt < 2; mt++)
                #pragma unroll
                for (int nt = 0; nt < 8; nt++) {
                    const uint32_t* bh = &bfh[nt >> 1][(nt & 1) * 2];
                    const uint32_t* bl = &bfl[nt >> 1][(nt & 1) * 2];
                    mma16816_bf(acc[mt][nt], afh[mt], bh);
                    mma16816_bf(acc[mt][nt], afh[mt], bl);
                    mma16816_bf(acc[mt][nt], afl[mt], bh);
                }
        }
        __syncthreads();
    }
    #pragma unroll
    for (int mt = 0; mt < 2; mt++) {
        int r0 = bm + wm + mt * 16 + (lane >> 2);
        #pragma unroll
        for (int nt = 0; nt < 8; nt++) {
            int n0 = bn + wn + nt * 8 + (lane & 3) * 2;
            float b0 = bias0[n0] + bias1[n0];
            float b1 = bias0[n0+1] + bias1[n0+1];
            C[(size_t)n0     * MROWS + r0]     = acc[mt][nt][0] + b0;
            C[(size_t)(n0+1) * MROWS + r0]     = acc[mt][nt][1] + b1;
            C[(size_t)n0     * MROWS + r0 + 8] = acc[mt][nt][2] + b0;
            C[(size_t)(n0+1) * MROWS + r0 + 8] = acc[mt][nt][3] + b1;
        }
    }
}

// ---- persistent LSTM v4: tensor-core recurrence (fp16 hi/lo 3-pass) --------
// 128 CTAs x 512 threads. CTA owns 16 gate-rows (n = g*4+jl -> W row g*512+cta*4+jl).
// Per step: gates[32b x 16n] = h[32,512] @ Wslice^T via mma; warps 0-1 k-split.
// smem: Wimg hi/lo 2x16KB | h planes hi/lo 2x32KB | gate partials 2x2KB = 100KB
#define LS_WH 0
#define LS_WL 16384
#define LS_HH 32768
#define LS_HL 65536
#define LS_G0 98304
#define LS_G1 100352
#define LS_SMEM 102400

__device__ __forceinline__ float sigmoidf_(float x) { return 1.f / (1.f + expf(-x)); }

__global__ __launch_bounds__(512)
void lstm_mma(const float* __restrict__ xwT, const float* __restrict__ W_hh,
              __half* __restrict__ hbh, __half* __restrict__ hbl,  // [2][16384]
              float* __restrict__ cbuf, float* __restrict__ ys,
              int* __restrict__ bar) {
    char* sm = dynsmem;
    uint32_t sb = s2u(sm);
    float* g0f = reinterpret_cast<float*>(sm + LS_G0);
    float* g1f = reinterpret_cast<float*>(sm + LS_G1);
    int tid = threadIdx.x, wid = tid >> 5, lane = tid & 31, cta = blockIdx.x;

    // build W image once: n=tid>>5 (0..15), 16 k per thread... (32 lanes x 16 k = 512)
    {
        int n = tid >> 5;
        int k0 = (tid & 31) * 16;
        int wrow = (n >> 2) * HH + cta * 4 + (n & 3);
        const float* wsrc = W_hh + (size_t)wrow * HH + k0;
        #pragma unroll
        for (int kk = 0; kk < 16; kk++) {
            float v = wsrc[kk];
            __half hi = __float2half_rn(v);
            __half lo = __float2half_rn(v - __half2float(hi));
            int k = k0 + kk;
            uint32_t off = (uint32_t)((k >> 6) * 2048) + SWZ((uint32_t)(n*128 + (k & 63)*2));
            *reinterpret_cast<__half*>(sm + LS_WH + off) = hi;
            *reinterpret_cast<__half*>(sm + LS_WL + off) = lo;
        }
    }
    float creg = 0.f;
    if (wid < 4) creg = cbuf[(cta*4 + wid)*32 + lane];
    __syncthreads();

    volatile int* vbar = (volatile int*)bar;

    for (int t = 0; t < TT; t++) {
        // owner xw prefetch (independent of h)
        float xwv0 = 0.f, xwv1 = 0.f, xwv2 = 0.f, xwv3 = 0.f;
        if (wid < 4) {
            int m = t*32 + lane, jg = cta*4 + wid;
            xwv0 = xwT[(size_t)(0*HH + jg) * MROWS + m];
            xwv1 = xwT[(size_t)(1*HH + jg) * MROWS + m];
            xwv2 = xwT[(size_t)(2*HH + jg) * MROWS + m];
            xwv3 = xwT[(size_t)(3*HH + jg) * MROWS + m];
        }
        // stage h planes: 4096 x 16B granules
        {
            const __half* sh = hbh + (t & 1) * (HH*BB);
            const __half* sl = hbl + (t & 1) * (HH*BB);
            #pragma unroll
            for (int it = 0; it < 8; it++) {
                int i = tid + it * 512;          // 0..4095
                int p = i >> 11, j = i & 2047;
                int b = j >> 6, kseg = j & 63;
                const __half* src = (p ? sl : sh) + b*512 + kseg*8;
                uint32_t dst = sb + (p ? LS_HL : LS_HH)
                             + (uint32_t)((kseg >> 3) * 4096)
                             + SWZ((uint32_t)(b*128 + (kseg & 7)*16));
                cp16(dst, src);
            }
            CP_COMMIT(); CP_WAIT0();
        }
        __syncthreads();

        // mma: warps 0-1, k-split (chunks of 64 k)
        if (wid < 2) {
            float acc[2][2][4];
            #pragma unroll
            for (int mt = 0; mt < 2; mt++)
                #pragma unroll
                for (int nt = 0; nt < 2; nt++)
                    #pragma unroll
                    for (int q = 0; q < 4; q++) acc[mt][nt][q] = 0.f;
            #pragma unroll
            for (int ci = 0; ci < 4; ci++) {
                int c = wid * 4 + ci;
                uint32_t ah_b = sb + LS_HH + c * 4096;
                uint32_t al_b = sb + LS_HL + c * 4096;
                uint32_t bh_b = sb + LS_WH + c * 2048;
                uint32_t bl_b = sb + LS_WL + c * 2048;
                #pragma unroll
                for (int kk = 0; kk < 4; kk++) {
                    uint32_t ah[2][4], al[2][4], bh[4], bl[4];
                    #pragma unroll
                    for (int mt = 0; mt < 2; mt++) {
                        int r = mt*16 + (lane & 15);
                        uint32_t off = SWZ((uint32_t)(r*128 + kk*32 + (lane >> 4)*16));
                        ldsm4(ah[mt], ah_b + off);
                        ldsm4(al[mt], al_b + off);
                    }
                    {
                        int nr = (lane & 7) + ((lane >> 4) << 3);
                        uint32_t off = SWZ((uint32_t)(nr*128 + kk*32 + ((lane >> 3) & 1)*16));
                        ldsm4(bh, bh_b + off);
                        ldsm4(bl, bl_b + off);
                    }
                    #pragma unroll
                    for (int mt = 0; mt < 2; mt++)
                        #pragma unroll
                        for (int nt = 0; nt < 2; nt++) {
                            mma16816_fp(acc[mt][nt], ah[mt], &bh[nt*2]);
                            mma16816_fp(acc[mt][nt], ah[mt], &bl[nt*2]);
                            mma16816_fp(acc[mt][nt], al[mt], &bh[nt*2]);
                        }
                }
            }
            float* gp = wid ? g1f : g0f;
            #pragma unroll
            for (int mt = 0; mt < 2; mt++)
                #pragma unroll
                for (int nt = 0; nt < 2; nt++) {
                    int r = mt*16 + (lane >> 2);
                    int c0 = nt*8 + (lane & 3)*2;
                    gp[r*16 + c0]       = acc[mt][nt][0];
                    gp[r*16 + c0 + 1]   = acc[mt][nt][1];
                    gp[(r+8)*16 + c0]   = acc[mt][nt][2];
                    gp[(r+8)*16 + c0+1] = acc[mt][nt][3];
                }
        }
        __syncthreads();

        // epilogue: owner (jl=wid<4, b=lane)
        if (wid < 4) {
            int b = lane, jl = wid, jg = cta*4 + jl;
            float ai = xwv0 + g0f[b*16 + jl]      + g1f[b*16 + jl];
            float af = xwv1 + g0f[b*16 + 4 + jl]  + g1f[b*16 + 4 + jl];
            float ag = xwv2 + g0f[b*16 + 8 + jl]  + g1f[b*16 + 8 + jl];
            float ao = xwv3 + g0f[b*16 + 12 + jl] + g1f[b*16 + 12 + jl];
            float ig = sigmoidf_(ai), fg = sigmoidf_(af);
            float gg = tanhf(ag),    og = sigmoidf_(ao);
            float c_new = fmaf(fg, creg, ig * gg);
            float h_new = og * tanhf(c_new);
            creg = c_new;
            __half hh = __float2half_rn(h_new);
            __half hl2 = __float2half_rn(h_new - __half2float(hh));
            int nidx = ((t+1) & 1) * (HH*BB) + b*512 + jg;
            hbh[nidx] = hh;
            hbl[nidx] = hl2;
            ys[(size_t)(t*32 + b) * HH + jg] = h_new;
            if (t == TT-1) cbuf[jg*32 + b] = creg;
            __threadfence();
        }
        __syncthreads();
        if (tid == 0) {
            atomicAdd(&bar[t], 1);
            while (vbar[t] < (int)gridDim.x) { }
            __threadfence();
        }
        __syncthreads();
    }
}

// ---- ctx: exact softmax shortcut = masked mean over S ----
__global__ void ctx_kernel(const float* __restrict__ enc, const int* __restrict__ src_mask,
                           float* __restrict__ ctx) {
    int b = blockIdx.x, h = threadIdx.x;
    float s_un = 0.f, s_all = 0.f; int cnt = 0;
    #pragma unroll 4
    for (int s = 0; s < SS; s++) {
        float v = enc[((size_t)s * BB + b) * HH + h];
        s_all += v;
        if (src_mask[s * BB + b] == 0) { s_un += v; cnt++; }
    }
    ctx[b * HH + h] = (cnt > 0) ? (s_un / (float)cnt) : (s_all / (float)SS);
}

// ---- fp16 single-pass logits GEMM (validated) ----
#define CHUNKS 16
#define BUFSTR2 (2*PLANE)
#define GSMEM_LG (2*BUFSTR2)     // 64 KB

__global__ __launch_bounds__(256, 1)
void gemm_logits_mma(const __half* __restrict__ Ah, const __half* __restrict__ Bh,
                     float* __restrict__ out) {
    uint32_t sb = s2u(dynsmem);
    int tid = threadIdx.x, wid = tid >> 5, lane = tid & 31;
    int bm = blockIdx.x * 128, bn = blockIdx.y * 128;
    int wm = (wid & 3) * 32, wn = (wid >> 2) * 64;

    float acc[2][8][4];
    #pragma unroll
    for (int mt = 0; mt < 2; mt++)
        #pragma unroll
        for (int nt = 0; nt < 8; nt++)
            #pragma unroll
            for (int q = 0; q < 4; q++) acc[mt][nt][q] = 0.f;

    const __half* gsrc[2] = {Ah, Bh};
    auto fill = [&](int c, int buf) {
        uint32_t base = sb + buf * BUFSTR2;
        #pragma unroll
        for (int it = 0; it < 8; it++) {
            int i = tid + it * 256;
            int p = i >> 10, j = i & 1023;
            int r = j >> 3, seg = j & 7;
            int grow = (p == 0) ? (bm + r) : (bn + r);
            const __half* g = gsrc[p] + ((size_t)grow << 10) + (c << 6) + (seg << 3);
            cp16(base + p * PLANE + SWZ((uint32_t)(r * 128 + seg * 16)), g);
        }
        CP_COMMIT();
    };

    fill(0, 0);
    for (int c = 0; c < CHUNKS; c++) {
        int buf = c & 1;
        if (c + 1 < CHUNKS) { fill(c + 1, buf ^ 1); CP_WAIT1(); }
        else                { CP_WAIT0(); }
        __syncthreads();
        uint32_t base = sb + buf * BUFSTR2;
        #pragma unroll
        for (int kk = 0; kk < 4; kk++) {
            uint32_t af[2][4];
            #pragma unroll
            for (int mt = 0; mt < 2; mt++) {
                int r = wm + mt * 16 + (lane & 15);
                uint32_t off = SWZ((uint32_t)(r * 128 + kk * 32 + (lane >> 4) * 16));
                ldsm4(af[mt], base + 0 * PLANE + off);
            }
            uint32_t bf[4][4];
            #pragma unroll
            for (int np = 0; np < 4; np++) {
                int nrow = wn + np * 16 + (lane & 7) + ((lane >> 4) << 3);
                uint32_t off = SWZ((uint32_t)(nrow * 128 + kk * 32 + ((lane >> 3) & 1) * 16));
                ldsm4(bf[np], base + 1 * PLANE + off);
            }
            #pragma unroll
            for (int mt = 0; mt < 2; mt++)
                #pragma unroll
                for (int nt = 0; nt < 8; nt++)
                    mma16816_fp(acc[mt][nt], af[mt], &bf[nt >> 1][(nt & 1) * 2]);
        }
        __syncthreads();
    }
    #pragma unroll
    for (int mt = 0; mt < 2; mt++) {
        int r0 = bm + wm + mt * 16 + (lane >> 2);
        #pragma unroll
        for (int nt = 0; nt < 8; nt++) {
            int cidx = bn + wn + nt * 8 + (lane & 3) * 2;
            *reinterpret_cast<float2*>(out + (size_t)r0 * VV + cidx) =
                make_float2(acc[mt][nt][0], acc[mt][nt][1]);
            *reinterpret_cast<float2*>(out + (size_t)(r0 + 8) * VV + cidx) =
                make_float2(acc[mt][nt][2], acc[mt][nt][3]);
        }
    }
}

// ---- tail: hs / cs ----
__global__ void tail_kernel(const float* __restrict__ ys0, const float* __restrict__ ys1,
                            const float* __restrict__ c0, const float* __restrict__ c1,
                            float* __restrict__ out) {
    int idx = blockIdx.x * blockDim.x + threadIdx.x;
    if (idx >= 4*HH*BB) return;
    int seg = idx >> 14, i = idx & 16383;
    int b = i >> 9, j = i & 511;
    float v;
    if      (seg == 0) v = ys0[((size_t)(TT-1)*BB + b) * HH + j];
    else if (seg == 1) v = ys1[((size_t)(TT-1)*BB + b) * HH + j];
    else if (seg == 2) v = c0[j*32 + b];
    else               v = c1[j*32 + b];
    out[(size_t)MROWS * VV + idx] = v;
}

// ---- launch ----
extern "C" void kernel_launch(void* const* d_in, const int* in_sizes, int n_in,
                              void* d_out, int out_size) {
    (void)in_sizes; (void)n_in; (void)out_size;
    const int*   tgt     = (const int*)  d_in[0];
    const float* hidden  = (const float*)d_in[1];
    const float* cell    = (const float*)d_in[2];
    const float* enc     = (const float*)d_in[3];
    const int*   srcmask = (const int*)  d_in[4];
    const float* emb     = (const float*)d_in[5];
    const float* Wih0    = (const float*)d_in[6];
    const float* Whh0    = (const float*)d_in[7];
    const float* bih0    = (const float*)d_in[8];
    const float* bhh0    = (const float*)d_in[9];
    const float* Wih1    = (const float*)d_in[10];
    const float* Whh1    = (const float*)d_in[11];
    const float* bih1    = (const float*)d_in[12];
    const float* bhh1    = (const float*)d_in[13];
    // d_in[14] = W1: provably irrelevant (softmax shortcut)
    const float* W2      = (const float*)d_in[15];
    float* out = (float*)d_out;

    float *p_x, *p_xw, *p_ys0, *p_ys1, *p_c0, *p_c1, *p_ctx;
    __half *p_h0h, *p_h0l, *p_h1h, *p_h1l, *p_Ah, *p_Wh;
    __nv_bfloat16 *p_xh, *p_xl, *p_wih_h, *p_wih_l;
    int *p_bar;
    cudaGetSymbolAddress((void**)&p_x,     g_x);
    cudaGetSymbolAddress((void**)&p_xw,    g_xw);
    cudaGetSymbolAddress((void**)&p_ys0,   g_ys0);
    cudaGetSymbolAddress((void**)&p_ys1,   g_ys1);
    cudaGetSymbolAddress((void**)&p_h0h,   g_h0h);
    cudaGetSymbolAddress((void**)&p_h0l,   g_h0l);
    cudaGetSymbolAddress((void**)&p_h1h,   g_h1h);
    cudaGetSymbolAddress((void**)&p_h1l,   g_h1l);
    cudaGetSymbolAddress((void**)&p_c0,    g_c0);
    cudaGetSymbolAddress((void**)&p_c1,    g_c1);
    cudaGetSymbolAddress((void**)&p_ctx,   g_ctx);
    cudaGetSymbolAddress((void**)&p_Ah,    g_Ah);
    cudaGetSymbolAddress((void**)&p_Wh,    g_Wh);
    cudaGetSymbolAddress((void**)&p_xh,    g_xh);
    cudaGetSymbolAddress((void**)&p_xl,    g_xl);
    cudaGetSymbolAddress((void**)&p_wih_h, g_wih_h);
    cudaGetSymbolAddress((void**)&p_wih_l, g_wih_l);
    cudaGetSymbolAddress((void**)&p_bar,   g_bar);

    cudaFuncSetAttribute(lstm_mma, cudaFuncAttributeMaxDynamicSharedMemorySize, LS_SMEM);
    cudaFuncSetAttribute(gemm_logits_mma, cudaFuncAttributeMaxDynamicSharedMemorySize, GSMEM_LG);
    cudaFuncSetAttribute(gemm_xw_mma, cudaFuncAttributeMaxDynamicSharedMemorySize, GSMEM_XW);

    init_state<<<64, 256>>>(hidden, cell, p_h0h, p_h0l, p_h1h, p_h1l, p_c0, p_c1, p_bar);
    gather_emb<<<MROWS, 128>>>(tgt, emb, p_x);
    conv_w_h<<<(int)(((size_t)VV*KTOT)/8/256), 256>>>(W2, p_Wh);

    // layer 0
    conv_flat<<<512, 256>>>(p_x, p_xh, p_xl);
    conv_flat<<<512, 256>>>(Wih0, p_wih_h, p_wih_l);
    gemm_xw_mma<<<dim3(16, 16), 256, GSMEM_XW>>>(p_xh, p_xl, p_wih_h, p_wih_l, p_xw, bih0, bhh0);
    lstm_mma<<<128, 512, LS_SMEM>>>(p_xw, Whh0, p_h0h, p_h0l, p_c0, p_ys0, p_bar);

    // layer 1
    conv_flat<<<512, 256>>>(p_ys0, p_xh, p_xl);
    conv_flat<<<512, 256>>>(Wih1, p_wih_h, p_wih_l);
    gemm_xw_mma<<<dim3(16, 16), 256, GSMEM_XW>>>(p_xh, p_xl, p_wih_h, p_wih_l, p_xw, bih1, bhh1);
    lstm_mma<<<128, 512, LS_SMEM>>>(p_xw, Whh1, p_h1h, p_h1l, p_c1, p_ys1, p_bar + TT);

    ctx_kernel<<<BB, HH>>>(enc, srcmask, p_ctx);
    conv_a_h<<<MROWS, 128>>>(p_ys1, p_ctx, p_Ah);
    gemm_logits_mma<<<dim3(MROWS/128, VV/128), 256, GSMEM_LG>>>(p_Ah, p_Wh, out);

    tail_kernel<<<64, 1024>>>(p_ys0, p_ys1, p_c0, p_c1, out);
}